// round 12
// baseline (speedup 1.0000x reference)
#include <cuda_runtime.h>
#include <cuda_fp16.h>
#include <cstdint>

// ---------------------------------------------------------------------------
// Problem constants
// ---------------------------------------------------------------------------
#define BROWS 4096
#define DDIM  4096
#define OROWS 4096
#define MBUCK 2048

#define GM 4096
#define GN 4096
#define GK 2048
#define BM 128
#define BN 128
#define BK 64
#define NKT (GK / BK)      // 32

// smem: 3 stages x (A 16KB + B 16KB)
#define A_TILE_B 16384
#define STAGE_B  32768
#define NSTAGE   3
#define SMEM_TOTAL (NSTAGE * STAGE_B)   // 98304; 2 CTAs/SM -> 192KB/SM

// ---------------------------------------------------------------------------
// Scratch panels (fp16, row-major [rows][2048])
// ---------------------------------------------------------------------------
__device__ __align__(16) __half g_A[(size_t)GM * GK];  // 16 MB
__device__ __align__(16) __half g_B[(size_t)GN * GK];  // 16 MB

// ---------------------------------------------------------------------------
// Sketch kernel v4: 4 rows per block, packed f16x2 shared atomics.
// blocks [0,1024) -> input rows -> g_A, [1024,2048) -> weight -> g_B.
// acc[0][j] = half2(row0, row1), acc[1][j] = half2(row2, row3).
// ---------------------------------------------------------------------------
__global__ __launch_bounds__(256) void sketch_kernel(
    const float* __restrict__ inA,
    const float* __restrict__ inB,
    const int*   __restrict__ hidx,
    const float* __restrict__ sgn)
{
    __shared__ __align__(16) __half2 acc[2][MBUCK];
    const int which = blockIdx.x >> 10;            // 0 -> A, 1 -> B
    const int row0  = (blockIdx.x & 1023) * 4;
    const float* x  = which ? inB : inA;
    const int tid = threadIdx.x;

    const float4* xr0 = (const float4*)(x + (size_t)(row0 + 0) * DDIM);
    const float4* xr1 = (const float4*)(x + (size_t)(row0 + 1) * DDIM);
    const float4* xr2 = (const float4*)(x + (size_t)(row0 + 2) * DDIM);
    const float4* xr3 = (const float4*)(x + (size_t)(row0 + 3) * DDIM);
    const int4*   h4  = (const int4*)hidx;
    const float4* s4  = (const float4*)sgn;

    const __half2 z = __halves2half2(__float2half(0.0f), __float2half(0.0f));
    for (int i = tid; i < 2 * MBUCK; i += 256) ((__half2*)acc)[i] = z;
    __syncthreads();

    #pragma unroll
    for (int it = 0; it < DDIM / 4 / 256; ++it) {   // 4 iters
        const int idx = it * 256 + tid;
        const float4 a  = xr0[idx];
        const float4 b  = xr1[idx];
        const float4 c  = xr2[idx];
        const float4 d  = xr3[idx];
        const int4   hv = h4[idx];
        const float4 sv = s4[idx];
        atomicAdd(&acc[0][hv.x], __floats2half2_rn(a.x * sv.x, b.x * sv.x));
        atomicAdd(&acc[1][hv.x], __floats2half2_rn(c.x * sv.x, d.x * sv.x));
        atomicAdd(&acc[0][hv.y], __floats2half2_rn(a.y * sv.y, b.y * sv.y));
        atomicAdd(&acc[1][hv.y], __floats2half2_rn(c.y * sv.y, d.y * sv.y));
        atomicAdd(&acc[0][hv.z], __floats2half2_rn(a.z * sv.z, b.z * sv.z));
        atomicAdd(&acc[1][hv.z], __floats2half2_rn(c.z * sv.z, d.z * sv.z));
        atomicAdd(&acc[0][hv.w], __floats2half2_rn(a.w * sv.w, b.w * sv.w));
        atomicAdd(&acc[1][hv.w], __floats2half2_rn(c.w * sv.w, d.w * sv.w));
    }
    __syncthreads();

    // unpack: 8 buckets per thread x 4 rows
    const int k0 = tid * 8;
    uint32_t w0[4], w1[4], w2[4], w3[4];
    #pragma unroll
    for (int j = 0; j < 4; ++j) {
        const __half2 p0 = acc[0][k0 + 2 * j];
        const __half2 p1 = acc[0][k0 + 2 * j + 1];
        const __half2 q0 = acc[1][k0 + 2 * j];
        const __half2 q1 = acc[1][k0 + 2 * j + 1];
        __half2 r0 = __halves2half2(__low2half(p0),  __low2half(p1));
        __half2 r1 = __halves2half2(__high2half(p0), __high2half(p1));
        __half2 r2 = __halves2half2(__low2half(q0),  __low2half(q1));
        __half2 r3 = __halves2half2(__high2half(q0), __high2half(q1));
        w0[j] = *(uint32_t*)&r0;
        w1[j] = *(uint32_t*)&r1;
        w2[j] = *(uint32_t*)&r2;
        w3[j] = *(uint32_t*)&r3;
    }
    __half* pan = which ? g_B : g_A;
    *(uint4*)(pan + (size_t)(row0 + 0) * GK + k0) = make_uint4(w0[0], w0[1], w0[2], w0[3]);
    *(uint4*)(pan + (size_t)(row0 + 1) * GK + k0) = make_uint4(w1[0], w1[1], w1[2], w1[3]);
    *(uint4*)(pan + (size_t)(row0 + 2) * GK + k0) = make_uint4(w2[0], w2[1], w2[2], w2[3]);
    *(uint4*)(pan + (size_t)(row0 + 3) * GK + k0) = make_uint4(w3[0], w3[1], w3[2], w3[3]);
}

// ---------------------------------------------------------------------------
// GEMM helpers
// ---------------------------------------------------------------------------
__device__ __forceinline__ uint32_t sm_u32(const void* p) {
    uint32_t r;
    asm("{ .reg .u64 t; cvta.to.shared.u64 t, %1; cvt.u32.u64 %0, t; }"
        : "=r"(r) : "l"(p));
    return r;
}

#define CP_ASYNC16(saddr, gaddr) \
    asm volatile("cp.async.cg.shared.global [%0], [%1], 16;" \
                 :: "r"(saddr), "l"(gaddr))
#define CP_COMMIT() asm volatile("cp.async.commit_group;")
#define CP_WAIT(n)  asm volatile("cp.async.wait_group %0;" :: "n"(n))

#define LDMATRIX_X4(r0, r1, r2, r3, addr) \
    asm volatile("ldmatrix.sync.aligned.m8n8.x4.shared.b16 {%0,%1,%2,%3}, [%4];" \
                 : "=r"(r0), "=r"(r1), "=r"(r2), "=r"(r3) : "r"(addr))

#define MMA_16816(d, a, b) \
    asm volatile("mma.sync.aligned.m16n8k16.row.col.f32.f16.f16.f32 " \
                 "{%0,%1,%2,%3}, {%4,%5,%6,%7}, {%8,%9}, {%0,%1,%2,%3};" \
                 : "+f"(d[0]), "+f"(d[1]), "+f"(d[2]), "+f"(d[3]) \
                 : "r"(a[0]), "r"(a[1]), "r"(a[2]), "r"(a[3]), \
                   "r"(b[0]), "r"(b[1]))

// ---------------------------------------------------------------------------
// GEMM-NT: C = A * B^T + bias. R9 skeleton (load-ahead-before-wait, two
// barriers per k-tile) deepened to 3 stages: cp.async gets 2 tiles of slack.
// ---------------------------------------------------------------------------
__global__ __launch_bounds__(256, 2) void gemm_kernel(
    const float* __restrict__ bias,
    float* __restrict__ C)
{
    extern __shared__ char smem[];
    const uint32_t sb = sm_u32(smem);
    const int tid  = threadIdx.x;
    const int wid  = tid >> 5;
    const int lane = tid & 31;
    const int wm = wid >> 1;
    const int wn = wid & 1;
    const int bm = blockIdx.y * BM;
    const int bn = blockIdx.x * BN;

    const __half* gA = g_A + (size_t)bm * GK;
    const __half* gB = g_B + (size_t)bn * GK;

    const int lr = tid >> 3;
    const int lc = tid & 7;

    float acc[2][8][4];
    #pragma unroll
    for (int mi = 0; mi < 2; ++mi)
        #pragma unroll
        for (int ni = 0; ni < 8; ++ni)
            #pragma unroll
            for (int j = 0; j < 4; ++j) acc[mi][ni][j] = 0.0f;

    uint32_t s_store[2][4];
    #pragma unroll
    for (int p = 0; p < 4; ++p) {
        int r = p * 32 + lr;
        uint32_t off = (uint32_t)r * 128 + (uint32_t)((lc ^ (r & 7)) << 4);
        s_store[0][p] = sb + off;
        s_store[1][p] = sb + A_TILE_B + off;
    }

    const int a_row0 = wm * 32 + (lane & 15);
    const int a_kcb  = lane >> 4;
    const int b_n0   = wn * 64 + ((lane >> 4) << 3) + (lane & 7);
    const int b_kcb  = (lane >> 3) & 1;

    #define LOAD_STAGE(slot, k)                                                \
        do {                                                                   \
            const __half* ga = gA + (size_t)(k) * BK;                          \
            const __half* gb = gB + (size_t)(k) * BK;                          \
            const uint32_t so = (uint32_t)(slot) * STAGE_B;                    \
            _Pragma("unroll")                                                  \
            for (int p = 0; p < 4; ++p) {                                      \
                int r = p * 32 + lr;                                           \
                CP_ASYNC16(s_store[0][p] + so,                                 \
                           (uint64_t)(ga + (size_t)r * GK + lc * 8));          \
                CP_ASYNC16(s_store[1][p] + so,                                 \
                           (uint64_t)(gb + (size_t)r * GK + lc * 8));          \
            }                                                                  \
            CP_COMMIT();                                                       \
        } while (0)

    LOAD_STAGE(0, 0);
    LOAD_STAGE(1, 1);

    int rd = 0;   // slot being computed this iteration
    int wr = 2;   // slot receiving the kt+2 load
    for (int kt = 0; kt < NKT; ++kt) {
        // Issue load-ahead BEFORE waiting (R9 ordering). Slot `wr` = (kt+2)%3
        // was last read at kt-1 and is protected by kt-1's trailing sync.
        if (kt + 2 < NKT) {
            LOAD_STAGE(wr, kt + 2);
            CP_WAIT(2);
        } else if (kt + 1 < NKT) {
            CP_WAIT(1);
        } else {
            CP_WAIT(0);
        }
        __syncthreads();

        const uint32_t sA = sb + (uint32_t)rd * STAGE_B;
        const uint32_t sB = sA + A_TILE_B;

        #pragma unroll
        for (int k16 = 0; k16 < BK / 16; ++k16) {
            const int kc_a = k16 * 2 + a_kcb;
            const int kc_b = k16 * 2 + b_kcb;

            uint32_t a[2][4];
            #pragma unroll
            for (int mi = 0; mi < 2; ++mi) {
                int row = a_row0 + mi * 16;
                uint32_t addr = sA + (uint32_t)row * 128
                              + (uint32_t)((kc_a ^ (row & 7)) << 4);
                LDMATRIX_X4(a[mi][0], a[mi][1], a[mi][2], a[mi][3], addr);
            }
            uint32_t b[8][2];
            #pragma unroll
            for (int nj = 0; nj < 4; ++nj) {
                int n = b_n0 + nj * 16;
                uint32_t addr = sB + (uint32_t)n * 128
                              + (uint32_t)((kc_b ^ (n & 7)) << 4);
                LDMATRIX_X4(b[nj * 2][0], b[nj * 2][1],
                            b[nj * 2 + 1][0], b[nj * 2 + 1][1], addr);
            }
            #pragma unroll
            for (int mi = 0; mi < 2; ++mi)
                #pragma unroll
                for (int ni = 0; ni < 8; ++ni)
                    MMA_16816(acc[mi][ni], a[mi], b[ni]);
        }
        __syncthreads();

        rd = (rd == NSTAGE - 1) ? 0 : rd + 1;
        wr = (wr == NSTAGE - 1) ? 0 : wr + 1;
    }

    #pragma unroll
    for (int mi = 0; mi < 2; ++mi) {
        const int r0 = bm + wm * 32 + mi * 16 + (lane >> 2);
        #pragma unroll
        for (int ni = 0; ni < 8; ++ni) {
            const int col = bn + wn * 64 + ni * 8 + (lane & 3) * 2;
            const float b0 = __ldg(bias + col);
            const float b1 = __ldg(bias + col + 1);
            float2 v0 = make_float2(acc[mi][ni][0] + b0, acc[mi][ni][1] + b1);
            float2 v1 = make_float2(acc[mi][ni][2] + b0, acc[mi][ni][3] + b1);
            *(float2*)(C + (size_t)r0 * GN + col)       = v0;
            *(float2*)(C + (size_t)(r0 + 8) * GN + col) = v1;
        }
    }
}

// ---------------------------------------------------------------------------
// Launch
// ---------------------------------------------------------------------------
extern "C" void kernel_launch(void* const* d_in, const int* in_sizes, int n_in,
                              void* d_out, int out_size)
{
    const float* input  = (const float*)d_in[0];
    const float* weight = (const float*)d_in[1];
    const float* bias   = (const float*)d_in[2];
    const int*   hidx   = (const int*)d_in[3];
    const float* sgn    = (const float*)d_in[4];
    float* out = (float*)d_out;

    sketch_kernel<<<2048, 256>>>(input, weight, hidx, sgn);

    cudaFuncSetAttribute(gemm_kernel,
                         cudaFuncAttributeMaxDynamicSharedMemorySize, SMEM_TOTAL);
    dim3 grid(GN / BN, GM / BM);  // 32 x 32
    gemm_kernel<<<grid, 256, SMEM_TOTAL>>>(bias, out);
}

// round 13
// speedup vs baseline: 1.5656x; 1.5656x over previous
#include <cuda_runtime.h>
#include <cuda_fp16.h>
#include <cstdint>

// ---------------------------------------------------------------------------
// Problem constants
// ---------------------------------------------------------------------------
#define BROWS 4096
#define DDIM  4096
#define OROWS 4096
#define MBUCK 2048

#define GM 4096
#define GN 4096
#define GK 2048
#define BM 128
#define BN 128
#define BK 64
#define NKT (GK / BK)      // 32

// smem: 2 stages x (A 16KB + B 16KB)   (R11 proven)
#define A_TILE_B 16384
#define STAGE_B  32768
#define SMEM_TOTAL (2 * STAGE_B)

// ---------------------------------------------------------------------------
// Scratch panels (fp16, row-major [rows][2048])
// ---------------------------------------------------------------------------
__device__ __align__(16) __half g_A[(size_t)GM * GK];  // 16 MB
__device__ __align__(16) __half g_B[(size_t)GN * GK];  // 16 MB

// ---------------------------------------------------------------------------
// Sketch kernel (R11 proven): 2 rows per block, packed f16x2 shared atomics.
// blocks [0,2048) -> input row-pairs -> g_A, [2048,4096) -> weight -> g_B.
// ---------------------------------------------------------------------------
__global__ __launch_bounds__(256) void sketch_kernel(
    const float* __restrict__ inA,
    const float* __restrict__ inB,
    const int*   __restrict__ hidx,
    const float* __restrict__ sgn)
{
    __shared__ __align__(16) __half2 acc[MBUCK];
    const int which = blockIdx.x >> 11;            // 0 -> A, 1 -> B
    const int row0  = (blockIdx.x & 2047) * 2;
    const float* x  = which ? inB : inA;
    const int tid = threadIdx.x;

    const float4* xr0 = (const float4*)(x + (size_t)row0 * DDIM);
    const float4* xr1 = (const float4*)(x + (size_t)(row0 + 1) * DDIM);
    const int4*   h4  = (const int4*)hidx;
    const float4* s4  = (const float4*)sgn;

    for (int i = tid; i < MBUCK; i += 256)
        acc[i] = __halves2half2(__float2half(0.0f), __float2half(0.0f));
    __syncthreads();

    #pragma unroll
    for (int it = 0; it < DDIM / 4 / 256; ++it) {   // 4 iters
        const int idx = it * 256 + tid;
        const float4 a  = xr0[idx];
        const float4 b  = xr1[idx];
        const int4   hv = h4[idx];
        const float4 sv = s4[idx];
        atomicAdd(&acc[hv.x], __floats2half2_rn(a.x * sv.x, b.x * sv.x));
        atomicAdd(&acc[hv.y], __floats2half2_rn(a.y * sv.y, b.y * sv.y));
        atomicAdd(&acc[hv.z], __floats2half2_rn(a.z * sv.z, b.z * sv.z));
        atomicAdd(&acc[hv.w], __floats2half2_rn(a.w * sv.w, b.w * sv.w));
    }
    __syncthreads();

    // unpack: 8 buckets per thread; .x -> row0, .y -> row1
    const int k0 = tid * 8;
    uint32_t r0w[4], r1w[4];
    #pragma unroll
    for (int j = 0; j < 4; ++j) {
        const __half2 p0 = acc[k0 + 2 * j];
        const __half2 p1 = acc[k0 + 2 * j + 1];
        __half2 q0 = __halves2half2(__low2half(p0),  __low2half(p1));   // row0
        __half2 q1 = __halves2half2(__high2half(p0), __high2half(p1));  // row1
        r0w[j] = *(uint32_t*)&q0;
        r1w[j] = *(uint32_t*)&q1;
    }
    __half* pan = which ? g_B : g_A;
    *(uint4*)(pan + (size_t)row0 * GK + k0)       = make_uint4(r0w[0], r0w[1], r0w[2], r0w[3]);
    *(uint4*)(pan + (size_t)(row0 + 1) * GK + k0) = make_uint4(r1w[0], r1w[1], r1w[2], r1w[3]);
}

// ---------------------------------------------------------------------------
// GEMM helpers
// ---------------------------------------------------------------------------
__device__ __forceinline__ uint32_t sm_u32(const void* p) {
    uint32_t r;
    asm("{ .reg .u64 t; cvta.to.shared.u64 t, %1; cvt.u32.u64 %0, t; }"
        : "=r"(r) : "l"(p));
    return r;
}

#define CP_ASYNC16(saddr, gaddr) \
    asm volatile("cp.async.cg.shared.global.L2::256B [%0], [%1], 16;" \
                 :: "r"(saddr), "l"(gaddr))
#define CP_COMMIT() asm volatile("cp.async.commit_group;")
#define CP_WAIT(n)  asm volatile("cp.async.wait_group %0;" :: "n"(n))

#define LDMATRIX_X4(r0, r1, r2, r3, addr) \
    asm volatile("ldmatrix.sync.aligned.m8n8.x4.shared.b16 {%0,%1,%2,%3}, [%4];" \
                 : "=r"(r0), "=r"(r1), "=r"(r2), "=r"(r3) : "r"(addr))

#define MMA_16816(d, a, b) \
    asm volatile("mma.sync.aligned.m16n8k16.row.col.f32.f16.f16.f32 " \
                 "{%0,%1,%2,%3}, {%4,%5,%6,%7}, {%8,%9}, {%0,%1,%2,%3};" \
                 : "+f"(d[0]), "+f"(d[1]), "+f"(d[2]), "+f"(d[3]) \
                 : "r"(a[0]), "r"(a[1]), "r"(a[2]), "r"(a[3]), \
                   "r"(b[0]), "r"(b[1]))

// ---------------------------------------------------------------------------
// GEMM-NT (R11/R9 proven, verbatim): C = A * B^T + bias
// 8 warps (4M x 2N), warp tile 32x64, BK=64, 2-stage cp.async, 2 CTAs/SM.
// ---------------------------------------------------------------------------
__global__ __launch_bounds__(256, 2) void gemm_kernel(
    const float* __restrict__ bias,
    float* __restrict__ C)
{
    extern __shared__ char smem[];
    const uint32_t sb = sm_u32(smem);
    const int tid  = threadIdx.x;
    const int wid  = tid >> 5;
    const int lane = tid & 31;
    const int wm = wid >> 1;
    const int wn = wid & 1;
    const int bm = blockIdx.y * BM;
    const int bn = blockIdx.x * BN;

    const __half* gA = g_A + (size_t)bm * GK;
    const __half* gB = g_B + (size_t)bn * GK;

    const int lr = tid >> 3;
    const int lc = tid & 7;

    float acc[2][8][4];
    #pragma unroll
    for (int mi = 0; mi < 2; ++mi)
        #pragma unroll
        for (int ni = 0; ni < 8; ++ni)
            #pragma unroll
            for (int j = 0; j < 4; ++j) acc[mi][ni][j] = 0.0f;

    uint32_t s_store[2][4];
    #pragma unroll
    for (int p = 0; p < 4; ++p) {
        int r = p * 32 + lr;
        uint32_t off = (uint32_t)r * 128 + (uint32_t)((lc ^ (r & 7)) << 4);
        s_store[0][p] = sb + off;
        s_store[1][p] = sb + A_TILE_B + off;
    }

    const int a_row0 = wm * 32 + (lane & 15);
    const int a_kcb  = lane >> 4;
    const int b_n0   = wn * 64 + ((lane >> 4) << 3) + (lane & 7);
    const int b_kcb  = (lane >> 3) & 1;

    #define LOAD_STAGE(slot, k)                                                \
        do {                                                                   \
            const __half* ga = gA + (size_t)(k) * BK;                          \
            const __half* gb = gB + (size_t)(k) * BK;                          \
            const uint32_t so = (uint32_t)(slot) * STAGE_B;                    \
            _Pragma("unroll")                                                  \
            for (int p = 0; p < 4; ++p) {                                      \
                int r = p * 32 + lr;                                           \
                CP_ASYNC16(s_store[0][p] + so,                                 \
                           (uint64_t)(ga + (size_t)r * GK + lc * 8));          \
                CP_ASYNC16(s_store[1][p] + so,                                 \
                           (uint64_t)(gb + (size_t)r * GK + lc * 8));          \
            }                                                                  \
            CP_COMMIT();                                                       \
        } while (0)

    LOAD_STAGE(0, 0);

    for (int kt = 0; kt < NKT; ++kt) {
        const int s = kt & 1;
        if (kt + 1 < NKT) {
            LOAD_STAGE(s ^ 1, kt + 1);
            CP_WAIT(1);
        } else {
            CP_WAIT(0);
        }
        __syncthreads();

        const uint32_t sA = sb + (uint32_t)s * STAGE_B;
        const uint32_t sB = sA + A_TILE_B;

        #pragma unroll
        for (int k16 = 0; k16 < BK / 16; ++k16) {
            const int kc_a = k16 * 2 + a_kcb;
            const int kc_b = k16 * 2 + b_kcb;

            uint32_t a[2][4];
            #pragma unroll
            for (int mi = 0; mi < 2; ++mi) {
                int row = a_row0 + mi * 16;
                uint32_t addr = sA + (uint32_t)row * 128
                              + (uint32_t)((kc_a ^ (row & 7)) << 4);
                LDMATRIX_X4(a[mi][0], a[mi][1], a[mi][2], a[mi][3], addr);
            }
            uint32_t b[8][2];
            #pragma unroll
            for (int nj = 0; nj < 4; ++nj) {
                int n = b_n0 + nj * 16;
                uint32_t addr = sB + (uint32_t)n * 128
                              + (uint32_t)((kc_b ^ (n & 7)) << 4);
                LDMATRIX_X4(b[nj * 2][0], b[nj * 2][1],
                            b[nj * 2 + 1][0], b[nj * 2 + 1][1], addr);
            }
            #pragma unroll
            for (int mi = 0; mi < 2; ++mi)
                #pragma unroll
                for (int ni = 0; ni < 8; ++ni)
                    MMA_16816(acc[mi][ni], a[mi], b[ni]);
        }
        __syncthreads();
    }

    #pragma unroll
    for (int mi = 0; mi < 2; ++mi) {
        const int r0 = bm + wm * 32 + mi * 16 + (lane >> 2);
        #pragma unroll
        for (int ni = 0; ni < 8; ++ni) {
            const int col = bn + wn * 64 + ni * 8 + (lane & 3) * 2;
            const float b0 = __ldg(bias + col);
            const float b1 = __ldg(bias + col + 1);
            float2 v0 = make_float2(acc[mi][ni][0] + b0, acc[mi][ni][1] + b1);
            float2 v1 = make_float2(acc[mi][ni][2] + b0, acc[mi][ni][3] + b1);
            *(float2*)(C + (size_t)r0 * GN + col)       = v0;
            *(float2*)(C + (size_t)(r0 + 8) * GN + col) = v1;
        }
    }
}

// ---------------------------------------------------------------------------
// Launch
// ---------------------------------------------------------------------------
extern "C" void kernel_launch(void* const* d_in, const int* in_sizes, int n_in,
                              void* d_out, int out_size)
{
    const float* input  = (const float*)d_in[0];
    const float* weight = (const float*)d_in[1];
    const float* bias   = (const float*)d_in[2];
    const int*   hidx   = (const int*)d_in[3];
    const float* sgn    = (const float*)d_in[4];
    float* out = (float*)d_out;

    sketch_kernel<<<4096, 256>>>(input, weight, hidx, sgn);

    cudaFuncSetAttribute(gemm_kernel,
                         cudaFuncAttributeMaxDynamicSharedMemorySize, SMEM_TOTAL);
    dim3 grid(GN / BN, GM / BM);  // 32 x 32
    gemm_kernel<<<grid, 256, SMEM_TOTAL>>>(bias, out);
}